// round 10
// baseline (speedup 1.0000x reference)
#include <cuda_runtime.h>
#include <cuda_bf16.h>
#include <cstdint>

// ---------------- problem constants ----------------
#define HH   2048
#define VV   32000
#define SS   2048
#define BB   2
#define TMm  1024
#define NSEGc 16
#define NTOK 6144          // 4096 main tokens + 2048 math tokens
#define NVC  125           // V chunks (256 cols each)
#define CE_NT 2            // 128-wide n-tiles per chunk
#define LDA 72             // smem row stride in bf16 (144 B) for adapter GEMMs

#define W_SCALE 256.0f
#define W_SINV  (1.0f / 256.0f)

// ce smem: per stage A(128x144B) + B(128x144B) = 36864; 3 stages = 110592
#define CE_STAGE_BYTES 36864u
#define CE_SMEM_BYTES (3 * 36864)

// ---------------- scratch (device globals; no allocs allowed) ----------------
__device__ __align__(16) uint8_t g_W8[(size_t)VV * HH];                 // 65.5 MB e4m3 (x256)
__device__ __align__(16) uint8_t g_h8[(size_t)BB * SS * HH];            // 4.2 MB e4m3
__device__ __align__(16) uint8_t g_t8[(size_t)BB * TMm * HH];           // 2.1 MB e4m3
__device__ __align__(16) __nv_bfloat16 g_hid[(size_t)BB * SS * HH];     // bf16 (adapter in)
__device__ __align__(16) __nv_bfloat16 g_Abf[(size_t)NSEGc * HH * 256];
__device__ __align__(16) __nv_bfloat16 g_Bbf[(size_t)NSEGc * 256 * HH];
__device__ __align__(16) __nv_bfloat16 g_inter[(size_t)NSEGc * 128 * 256];
__device__ __align__(16) __nv_bfloat16 g_trans[(size_t)BB * TMm * HH];  // bf16 (labeldot)
__device__ float g_pm[NVC * NTOK];
__device__ float g_ps[NVC * NTOK];
__device__ float g_ld[NTOK];
__device__ float g_nll[NTOK];

// ---------------- helpers ----------------
__device__ __forceinline__ uint32_t smem_u32(const void* p) {
    return (uint32_t)__cvta_generic_to_shared(p);
}
__device__ __forceinline__ void ldsm4(uint32_t* r, uint32_t a) {
    asm volatile("ldmatrix.sync.aligned.m8n8.x4.shared.b16 {%0,%1,%2,%3}, [%4];"
                 : "=r"(r[0]), "=r"(r[1]), "=r"(r[2]), "=r"(r[3]) : "r"(a));
}
__device__ __forceinline__ void mma_bf16(float* d, const uint32_t* a, const uint32_t* b) {
    asm volatile(
        "mma.sync.aligned.m16n8k16.row.col.f32.bf16.bf16.f32 "
        "{%0,%1,%2,%3},{%4,%5,%6,%7},{%8,%9},{%0,%1,%2,%3};"
        : "+f"(d[0]), "+f"(d[1]), "+f"(d[2]), "+f"(d[3])
        : "r"(a[0]), "r"(a[1]), "r"(a[2]), "r"(a[3]), "r"(b[0]), "r"(b[1]));
}
__device__ __forceinline__ void mma_fp8(float* d, const uint32_t* a, const uint32_t* b) {
    asm volatile(
        "mma.sync.aligned.m16n8k32.row.col.f32.e4m3.e4m3.f32 "
        "{%0,%1,%2,%3},{%4,%5,%6,%7},{%8,%9},{%0,%1,%2,%3};"
        : "+f"(d[0]), "+f"(d[1]), "+f"(d[2]), "+f"(d[3])
        : "r"(a[0]), "r"(a[1]), "r"(a[2]), "r"(a[3]), "r"(b[0]), "r"(b[1]));
}
__device__ __forceinline__ void cp16(uint32_t s, const void* g) {
    asm volatile("cp.async.cg.shared.global [%0], [%1], 16;"
                 :: "r"(s), "l"(g) : "memory");
}
__device__ __forceinline__ void cp_commit() {
    asm volatile("cp.async.commit_group;" ::: "memory");
}
template <int N>
__device__ __forceinline__ void cp_wait() {
    asm volatile("cp.async.wait_group %0;" :: "n"(N) : "memory");
}
// pack float4 -> 4 e4m3 bytes (v.x at lowest byte)
__device__ __forceinline__ uint32_t pack_e4m3(float4 v) {
    uint16_t lo, hi;
    asm("cvt.rn.satfinite.e4m3x2.f32 %0, %1, %2;" : "=h"(lo) : "f"(v.y), "f"(v.x));
    asm("cvt.rn.satfinite.e4m3x2.f32 %0, %1, %2;" : "=h"(hi) : "f"(v.w), "f"(v.z));
    return (uint32_t)lo | ((uint32_t)hi << 16);
}
__device__ __forceinline__ uint16_t pack2_e4m3(float a, float b) {
    uint16_t r;
    asm("cvt.rn.satfinite.e4m3x2.f32 %0, %1, %2;" : "=h"(r) : "f"(b), "f"(a));
    return r;
}

// HMMA 16x128 warp-tile k-slab (small adapter GEMMs)
__device__ __forceinline__ void mma_ktile(float acc[16][4], const __nv_bfloat16* sA,
                                          const __nv_bfloat16* sB, int lane, int mbase) {
#pragma unroll
    for (int kk = 0; kk < 64; kk += 16) {
        uint32_t a[4];
        ldsm4(a, smem_u32(sA + (mbase + (lane & 15)) * LDA + kk + ((lane >> 4) << 3)));
#pragma unroll
        for (int jp = 0; jp < 8; jp++) {
            uint32_t b[4];
            ldsm4(b, smem_u32(sB + ((jp * 2 + (lane >> 4)) * 8 + (lane & 7)) * LDA
                              + kk + (((lane >> 3) & 1) << 3)));
            mma_bf16(acc[2 * jp], a, b);
            mma_bf16(acc[2 * jp + 1], a, b + 2);
        }
    }
}
__device__ __forceinline__ void load_tile128(__nv_bfloat16* s, const __nv_bfloat16* g,
                                             int ldg, int tid) {
#pragma unroll
    for (int i = 0; i < 4; i++) {
        int idx = tid + i * 256;
        int row = idx >> 3, c = idx & 7;
        uint4 v = *reinterpret_cast<const uint4*>(g + (size_t)row * ldg + c * 8);
        *reinterpret_cast<uint4*>((char*)s + row * 144 + c * 16) = v;
    }
}

// ---------------- kernel 1: conversions ----------------
// W fp32 -> e4m3 (x256). hid fp32 -> bf16 + e4m3. Am/Bm fp32 -> bf16.
__global__ void convert_all(const float4* __restrict__ W, const float4* __restrict__ hid,
                            const float4* __restrict__ Am, const float4* __restrict__ Bm) {
    const size_t NW = (size_t)VV * HH / 4;
    const size_t NH = (size_t)BB * SS * HH / 4;
    const size_t NA = (size_t)NSEGc * HH * 256 / 4;
    size_t gid = (size_t)blockIdx.x * 256 + threadIdx.x;
    if (gid < NW) {
        float4 v = W[gid];
        v.x *= W_SCALE; v.y *= W_SCALE; v.z *= W_SCALE; v.w *= W_SCALE;
        reinterpret_cast<uint32_t*>(g_W8)[gid] = pack_e4m3(v);
        return;
    }
    float4 v;
    __nv_bfloat162* dst;
    if (gid < NW + NH) {
        size_t i = gid - NW;
        v = hid[i];
        reinterpret_cast<uint32_t*>(g_h8)[i] = pack_e4m3(v);
        dst = (__nv_bfloat162*)g_hid + i * 2;
    } else if (gid < NW + NH + NA)     { size_t i = gid - NW - NH;      v = Am[i]; dst = (__nv_bfloat162*)g_Abf + i * 2; }
    else if (gid < NW + NH + 2 * NA)   { size_t i = gid - NW - NH - NA; v = Bm[i]; dst = (__nv_bfloat162*)g_Bbf + i * 2; }
    else return;
    __nv_bfloat162 p0, p1;
    p0.x = __float2bfloat16_rn(v.x); p0.y = __float2bfloat16_rn(v.y);
    p1.x = __float2bfloat16_rn(v.z); p1.y = __float2bfloat16_rn(v.w);
    dst[0] = p0; dst[1] = p1;
}

// ---------------- kernel 2: inter = gathered_x @ B_s^T ----------------
__global__ void __launch_bounds__(256, 2) gemm1_kernel(const int* __restrict__ starts) {
    __shared__ __nv_bfloat16 sA[128 * LDA];
    __shared__ __nv_bfloat16 sB[128 * LDA];
    int s = blockIdx.x >> 1, n0 = (blockIdx.x & 1) * 128;
    int tid = threadIdx.x, lane = tid & 31, warp = tid >> 5, mbase = warp * 16;
    int st0 = starts[0], st1 = starts[1];
    const __nv_bfloat16* Bbase = g_Bbf + ((size_t)s * 256 + n0) * HH;
    float acc[16][4];
#pragma unroll
    for (int j = 0; j < 16; j++) { acc[j][0] = acc[j][1] = acc[j][2] = acc[j][3] = 0.f; }
    for (int k0 = 0; k0 < HH; k0 += 64) {
        __syncthreads();
#pragma unroll
        for (int i = 0; i < 4; i++) {
            int idx = tid + i * 256;
            int row = idx >> 3, c = idx & 7;
            int b = row >> 6;
            int pos = (b ? st1 : st0) + s * 64 + (row & 63);
            uint4 v = *reinterpret_cast<const uint4*>(
                g_hid + ((size_t)(b * SS + pos)) * HH + k0 + c * 8);
            *reinterpret_cast<uint4*>((char*)sA + row * 144 + c * 16) = v;
        }
        load_tile128(sB, Bbase + k0, HH, tid);
        __syncthreads();
        mma_ktile(acc, sA, sB, lane, mbase);
    }
    int g = lane >> 2, t4 = lane & 3;
    int r0 = mbase + g;
#pragma unroll
    for (int j = 0; j < 16; j++) {
        int col = n0 + 8 * j + 2 * t4;
        __nv_bfloat162 v01, v23;
        v01.x = __float2bfloat16_rn(acc[j][0]); v01.y = __float2bfloat16_rn(acc[j][1]);
        v23.x = __float2bfloat16_rn(acc[j][2]); v23.y = __float2bfloat16_rn(acc[j][3]);
        *reinterpret_cast<__nv_bfloat162*>(&g_inter[((size_t)s * 128 + r0) * 256 + col]) = v01;
        *reinterpret_cast<__nv_bfloat162*>(&g_inter[((size_t)s * 128 + r0 + 8) * 256 + col]) = v23;
    }
}

// ---------------- kernel 3: trans = inter @ A_s^T + bias (bf16 + fp8 out) ----------------
__global__ void __launch_bounds__(256, 2) gemm2_kernel(const float* __restrict__ bias) {
    __shared__ __nv_bfloat16 sA[128 * LDA];
    __shared__ __nv_bfloat16 sB[128 * LDA];
    int s = blockIdx.x >> 4, n0 = (blockIdx.x & 15) * 128;
    int tid = threadIdx.x, lane = tid & 31, warp = tid >> 5, mbase = warp * 16;
    const __nv_bfloat16* Aba = g_inter + (size_t)s * 128 * 256;
    const __nv_bfloat16* Bba = g_Abf + ((size_t)s * HH + n0) * 256;
    float acc[16][4];
#pragma unroll
    for (int j = 0; j < 16; j++) { acc[j][0] = acc[j][1] = acc[j][2] = acc[j][3] = 0.f; }
    for (int k0 = 0; k0 < 256; k0 += 64) {
        __syncthreads();
        load_tile128(sA, Aba + k0, 256, tid);
        load_tile128(sB, Bba + k0, 256, tid);
        __syncthreads();
        mma_ktile(acc, sA, sB, lane, mbase);
    }
    int g = lane >> 2, t4 = lane & 3;
    int r0 = mbase + g, r1 = r0 + 8;
    int tok0r = (r0 >> 6) * TMm + s * 64 + (r0 & 63);
    int tok1r = (r1 >> 6) * TMm + s * 64 + (r1 & 63);
#pragma unroll
    for (int j = 0; j < 16; j++) {
        int col = n0 + 8 * j + 2 * t4;
        float b0 = bias[s * HH + col], b1 = bias[s * HH + col + 1];
        float f00 = acc[j][0] + b0, f01 = acc[j][1] + b1;
        float f10 = acc[j][2] + b0, f11 = acc[j][3] + b1;
        __nv_bfloat162 v01, v23;
        v01.x = __float2bfloat16_rn(f00); v01.y = __float2bfloat16_rn(f01);
        v23.x = __float2bfloat16_rn(f10); v23.y = __float2bfloat16_rn(f11);
        *reinterpret_cast<__nv_bfloat162*>(&g_trans[(size_t)tok0r * HH + col]) = v01;
        *reinterpret_cast<__nv_bfloat162*>(&g_trans[(size_t)tok1r * HH + col]) = v23;
        *reinterpret_cast<uint16_t*>(&g_t8[(size_t)tok0r * HH + col]) = pack2_e4m3(f00, f01);
        *reinterpret_cast<uint16_t*>(&g_t8[(size_t)tok1r * HH + col]) = pack2_e4m3(f10, f11);
    }
}

// ---------------- kernel 4: fp8 fused logits + online logsumexp ----------------
// grid = (48 M-tiles of 128 tokens, 125 V-chunks of 256 cols). 256 threads, 2 CTAs/SM.
// K-slab = 128 fp8 elements (128 B/row); mma.m16n8k32.e4m3; warp tile 32x64.
__global__ void __launch_bounds__(256, 2) ce_kernel(const int* __restrict__ starts) {
    extern __shared__ char dsm[];
    const uint32_t sbase = smem_u32(dsm);
    int mtile = blockIdx.x, chunk = blockIdx.y;
    int tid = threadIdx.x, wid = tid >> 5, lane = tid & 31;
    int wm = wid >> 1, wn = wid & 1, mbase = wm * 32;

    const uint8_t* Abase;
    if (mtile < 32) {
        int b = mtile >> 4, t0 = (mtile & 15) * 128;
        if (t0 + 127 < starts[b] - 1) return;   // tile entirely outside both masks
        Abase = g_h8 + (size_t)mtile * 128 * HH;
    } else {
        Abase = g_t8 + (size_t)(mtile - 32) * 128 * HH;
    }
    int tok0 = mtile * 128;
    const uint8_t* Bchunk = g_W8 + (size_t)(chunk * CE_NT * 128) * HH;
    const int TOT = CE_NT * 16;            // 16 K-slabs per n-tile

    auto issue = [&](int s) {
        uint32_t sa = sbase + (uint32_t)(s % 3) * CE_STAGE_BYTES;
        uint32_t sb = sa + 18432u;
        int k0 = (s & 15) * 128;           // byte offset in K
        const uint8_t* Asrc = Abase + k0;
        const uint8_t* Bsrc = Bchunk + (size_t)((s >> 4) * 128) * HH + k0;
#pragma unroll
        for (int i = 0; i < 4; i++) {      // A: 128 rows x 128 B
            int idx = tid + i * 256;
            int r = idx >> 3, c = idx & 7;
            cp16(sa + (uint32_t)(r * 144 + c * 16), Asrc + (size_t)r * HH + c * 16);
        }
#pragma unroll
        for (int i = 0; i < 4; i++) {      // B: 128 vocab rows x 128 B
            int idx = tid + i * 256;
            int r = idx >> 3, c = idx & 7;
            cp16(sb + (uint32_t)(r * 144 + c * 16), Bsrc + (size_t)r * HH + c * 16);
        }
        cp_commit();
    };

    float rm[4] = {-1e30f, -1e30f, -1e30f, -1e30f};
    float rs[4] = {0.f, 0.f, 0.f, 0.f};

    issue(0);
    issue(1);

    for (int nt = 0; nt < CE_NT; nt++) {
        float acc[2][8][4];
#pragma unroll
        for (int mi = 0; mi < 2; mi++)
#pragma unroll
            for (int j = 0; j < 8; j++) {
                acc[mi][j][0] = acc[mi][j][1] = acc[mi][j][2] = acc[mi][j][3] = 0.f;
            }
        for (int sl = 0; sl < 16; sl++) {
            int s = nt * 16 + sl;
            if (s < TOT - 1) cp_wait<1>(); else cp_wait<0>();
            __syncthreads();               // slab s ready; compute(s-1) done everywhere
            if (s + 2 < TOT) issue(s + 2);
            uint32_t sa = sbase + (uint32_t)(s % 3) * CE_STAGE_BYTES;
            uint32_t sb = sa + 18432u;
#pragma unroll
            for (int ks = 0; ks < 4; ks++) {   // 4 x k32 per 128B slab
                uint32_t a0[4], a1[4];
                uint32_t arow = (uint32_t)(mbase + (lane & 15));
                uint32_t abyte = (uint32_t)(ks * 32 + ((lane >> 4) << 4));
                ldsm4(a0, sa + arow * 144 + abyte);
                ldsm4(a1, sa + (arow + 16) * 144 + abyte);
#pragma unroll
                for (int jp = 0; jp < 4; jp++) {
                    uint32_t b[4];
                    uint32_t brow = (uint32_t)(wn * 64 + jp * 16 + ((lane >> 4) << 3) + (lane & 7));
                    uint32_t bbyte = (uint32_t)(ks * 32 + (((lane >> 3) & 1) << 4));
                    ldsm4(b, sb + brow * 144 + bbyte);
                    mma_fp8(acc[0][2 * jp], a0, b);
                    mma_fp8(acc[0][2 * jp + 1], a0, b + 2);
                    mma_fp8(acc[1][2 * jp], a1, b);
                    mma_fp8(acc[1][2 * jp + 1], a1, b + 2);
                }
            }
        }
        // descale, then online logsumexp; 4 row-streams per thread
#pragma unroll
        for (int mi = 0; mi < 2; mi++) {
#pragma unroll
            for (int j = 0; j < 8; j++) {
                acc[mi][j][0] *= W_SINV; acc[mi][j][1] *= W_SINV;
                acc[mi][j][2] *= W_SINV; acc[mi][j][3] *= W_SINV;
            }
            float m0 = -1e30f, m1 = -1e30f;
#pragma unroll
            for (int j = 0; j < 8; j++) {
                m0 = fmaxf(m0, fmaxf(acc[mi][j][0], acc[mi][j][1]));
                m1 = fmaxf(m1, fmaxf(acc[mi][j][2], acc[mi][j][3]));
            }
            m0 = fmaxf(m0, __shfl_xor_sync(0xffffffffu, m0, 1));
            m0 = fmaxf(m0, __shfl_xor_sync(0xffffffffu, m0, 2));
            m1 = fmaxf(m1, __shfl_xor_sync(0xffffffffu, m1, 1));
            m1 = fmaxf(m1, __shfl_xor_sync(0xffffffffu, m1, 2));
            float nm0 = fmaxf(rm[mi * 2], m0), nm1 = fmaxf(rm[mi * 2 + 1], m1);
            float s0 = 0.f, s1 = 0.f;
#pragma unroll
            for (int j = 0; j < 8; j++) {
                s0 += __expf(acc[mi][j][0] - nm0) + __expf(acc[mi][j][1] - nm0);
                s1 += __expf(acc[mi][j][2] - nm1) + __expf(acc[mi][j][3] - nm1);
            }
            s0 += __shfl_xor_sync(0xffffffffu, s0, 1);
            s0 += __shfl_xor_sync(0xffffffffu, s0, 2);
            s1 += __shfl_xor_sync(0xffffffffu, s1, 1);
            s1 += __shfl_xor_sync(0xffffffffu, s1, 2);
            rs[mi * 2] = rs[mi * 2] * __expf(rm[mi * 2] - nm0) + s0;
            rs[mi * 2 + 1] = rs[mi * 2 + 1] * __expf(rm[mi * 2 + 1] - nm1) + s1;
            rm[mi * 2] = nm0;
            rm[mi * 2 + 1] = nm1;
        }
    }
    // combine the two col-half warps (wn=0/1) that own the same rows
    __syncthreads();
    float2* ex = (float2*)dsm;
    int g = lane >> 2;
    if (wn == 1 && (lane & 3) == 0) {
#pragma unroll
        for (int k = 0; k < 4; k++) {
            float2 v; v.x = rm[k]; v.y = rs[k];
            ex[mbase + g + k * 8] = v;
        }
    }
    __syncthreads();
    if (wn == 0 && (lane & 3) == 0) {
#pragma unroll
        for (int k = 0; k < 4; k++) {
            int row = mbase + g + k * 8;
            float2 o = ex[row];
            float m = fmaxf(rm[k], o.x);
            float s = rs[k] * __expf(rm[k] - m) + o.y * __expf(o.x - m);
            g_pm[chunk * NTOK + tok0 + row] = m;
            g_ps[chunk * NTOK + tok0 + row] = s;
        }
    }
}

// ---------------- kernel 5: label logits (exact fp32) ----------------
__global__ void __launch_bounds__(256) labeldot_kernel(const int* __restrict__ ids,
                                                       const int* __restrict__ mlab,
                                                       const float* __restrict__ lhs,
                                                       const float* __restrict__ W) {
    int tok = blockIdx.x * 8 + (threadIdx.x >> 5);
    int lane = threadIdx.x & 31;
    int label;
    float acc = 0.f;
    if (tok < 4096) {
        int b = tok >> 11, t = tok & 2047;
        if (t >= 2047) { if (!lane) g_ld[tok] = 0.f; return; }
        label = ids[b * SS + t + 1];
        const float4* x4 = (const float4*)(lhs + (size_t)tok * HH);
        const float4* w4 = (const float4*)(W + (size_t)label * HH);
        for (int i = lane; i < HH / 4; i += 32) {
            float4 a = x4[i], b4 = w4[i];
            acc += a.x * b4.x + a.y * b4.y + a.z * b4.z + a.w * b4.w;
        }
    } else {
        label = mlab[tok - 4096];
        const __nv_bfloat162* x2 = (const __nv_bfloat162*)(g_trans + (size_t)(tok - 4096) * HH);
        const float2* w2 = (const float2*)(W + (size_t)label * HH);
        for (int i = lane; i < HH / 2; i += 32) {
            float2 a = __bfloat1622float2(x2[i]);
            float2 b4 = w2[i];
            acc += a.x * b4.x + a.y * b4.y;
        }
    }
#pragma unroll
    for (int o = 16; o; o >>= 1) acc += __shfl_xor_sync(0xffffffffu, acc, o);
    if (!lane) g_ld[tok] = acc;
}

// ---------------- kernel 5b: combine 125 chunk partials -> per-token nll ----------------
__global__ void __launch_bounds__(256) nll_kernel() {
    int tok = blockIdx.x * 256 + threadIdx.x;
    if (tok >= NTOK) return;
    float m = -1e30f;
    for (int c = 0; c < NVC; c++) m = fmaxf(m, g_pm[c * NTOK + tok]);
    float s = 0.f;
    for (int c = 0; c < NVC; c++)
        s += g_ps[c * NTOK + tok] * __expf(g_pm[c * NTOK + tok] - m);
    g_nll[tok] = __logf(s) + m - g_ld[tok];
}

// ---------------- kernel 6: masked means ----------------
__global__ void __launch_bounds__(256) reduce_kernel(const int* __restrict__ starts,
                                                     const int* __restrict__ ends,
                                                     const int* __restrict__ attn,
                                                     const int* __restrict__ mmask,
                                                     float* __restrict__ out) {
    __shared__ int rl[2];
    __shared__ double red[6];
    int tid = threadIdx.x;
    if (tid < 2) rl[tid] = 0;
    if (tid < 6) red[tid] = 0.0;
    __syncthreads();
    int l0 = 0, l1 = 0;
    for (int i = tid; i < SS; i += 256) { l0 += attn[i]; l1 += attn[SS + i]; }
    atomicAdd(&rl[0], l0);
    atomicAdd(&rl[1], l1);
    __syncthreads();
    double s_st = 0, c_st = 0, s_fa = 0, c_fa = 0, s_m = 0, c_m = 0;
    for (int tok = tid; tok < NTOK; tok += 256) {
        float w_st = 0.f, w_fa = 0.f, w_m = 0.f;
        if (tok < 4096) {
            int b = tok >> 11, t = tok & 2047;
            if (t <= SS - 2) {
                if (t >= starts[b] - 1 && t <= ends[b] - 1) w_st = 1.f;
                if (t >= ends[b] && t < rl[b] - 1) w_fa = 1.f;
            }
        } else {
            if (mmask[tok - 4096]) w_m = 1.f;
        }
        if (w_st + w_fa + w_m > 0.f) {
            float nll = g_nll[tok];
            s_st += (double)(nll * w_st); c_st += w_st;
            s_fa += (double)(nll * w_fa); c_fa += w_fa;
            s_m  += (double)(nll * w_m);  c_m  += w_m;
        }
    }
    atomicAdd(&red[0], s_st); atomicAdd(&red[1], c_st);
    atomicAdd(&red[2], s_fa); atomicAdd(&red[3], c_fa);
    atomicAdd(&red[4], s_m);  atomicAdd(&red[5], c_m);
    __syncthreads();
    if (tid == 0) {
        double st = red[0] / fmax(red[1], 1.0);
        double fa = red[2] / fmax(red[3], 1.0);
        double ml = red[4] / fmax(red[5], 1.0);
        out[0] = (float)(0.5 * ml + 0.5 * st + 0.4 * fa);
        out[1] = (float)ml;
        out[2] = (float)st;
        out[3] = (float)fa;
    }
}

// ---------------- launch ----------------
extern "C" void kernel_launch(void* const* d_in, const int* in_sizes, int n_in,
                              void* d_out, int out_size) {
    const float* lhs    = (const float*)d_in[0];
    const int*   ids    = (const int*)d_in[1];
    const int*   attn   = (const int*)d_in[2];
    const int*   starts = (const int*)d_in[3];
    const int*   ends   = (const int*)d_in[4];
    const int*   mlab   = (const int*)d_in[5];
    const int*   mmask  = (const int*)d_in[6];
    const float* Am     = (const float*)d_in[8];
    const float* Bm     = (const float*)d_in[9];
    const float* bias   = (const float*)d_in[10];
    const float* W      = (const float*)d_in[11];
    float* out = (float*)d_out;

    cudaFuncSetAttribute(ce_kernel, cudaFuncAttributeMaxDynamicSharedMemorySize,
                         CE_SMEM_BYTES);

    convert_all<<<88576, 256>>>((const float4*)W, (const float4*)lhs,
                                (const float4*)Am, (const float4*)Bm);
    gemm1_kernel<<<32, 256>>>(starts);
    gemm2_kernel<<<256, 256>>>(bias);
    ce_kernel<<<dim3(48, NVC), 256, CE_SMEM_BYTES>>>(starts);
    labeldot_kernel<<<768, 256>>>(ids, mlab, lhs, W);
    nll_kernel<<<24, 256>>>();
    reduce_kernel<<<1, 256>>>(starts, ends, attn, mmask, out);
    (void)in_sizes; (void)n_in; (void)out_size;
}